// round 16
// baseline (speedup 1.0000x reference)
#include <cuda_runtime.h>

// ChannelDropout — FINAL candidate: half-row blocks + streaming hints.
//   Grid 34944 (one block of 128 thr per half-row of 375 float4), the
//   measured-best geometry (kernel 56.5us, DRAM 78.3%), combined with
//   __ldcs/__stcs no-reuse hints on the 350MB stream (the one untested
//   cell in the matrix). kept(row) from pos+center computed first;
//   dropped rows (~10%) write zeros without reading signal. MC keep
//   probability via 4 warp ballots — no smem, no barriers.
//   Everything else in the design space measured neutral or worse:
//   persistent grids (-10%), LDG.256 (-9%), L2 evict_last pinning (0),
//   MLP 6 (0), 2 rows/block (0).

#define DROPOUT2 0.04f   // 0.2^2
#define EPSILON  1e-8f
#define H4       375     // float4 per half-row
#define ROWS     (64 * 273)   // 17472

__global__ __launch_bounds__(128, 16)
void fused_kernel(const float* __restrict__ sig,
                  const float2* __restrict__ pos2,
                  const float* __restrict__ center,
                  const float* __restrict__ mc,
                  float* __restrict__ out)
{
    const int blk  = blockIdx.x;           // 0 .. 34943
    const int row  = blk >> 1;             // 0 .. 17471
    const int half = blk & 1;
    const int tid  = threadIdx.x;          // 0 .. 127
    const int lane = tid & 31;

    const size_t base = (size_t)row * (2 * H4) + (size_t)half * H4;
    float4* __restrict__ o4 = (float4*)(out) + base;

    const int i0 = tid;
    const int i1 = tid + 128;
    const int i2 = tid + 256;
    const bool has2 = (i2 < H4);           // tid < 119

    // --- kept check first: only pos + center (block-uniform branch) ---
    const float2 p  = __ldg(&pos2[row]);
    const float cx = __ldg(&center[0]);
    const float cy = __ldg(&center[1]);

    const float dx = p.x - cx, dy = p.y - cy;
    const bool kept = (dx * dx + dy * dy) > DROPOUT2;

    if (!kept) {
        // Dropped half-row: zero output, skip signal reads AND MC work.
        const float4 z = make_float4(0.f, 0.f, 0.f, 0.f);
        __stcs(&o4[i0], z);
        __stcs(&o4[i1], z);
        if (has2) __stcs(&o4[i2], z);
        return;
    }

    // --- kept half-row: front-batch the 3 signal loads (no-reuse hint) ---
    const float4* __restrict__ s4 = (const float4*)(sig) + base;
    float4 v0 = __ldcs(&s4[i0]);
    float4 v1 = __ldcs(&s4[i1]);
    float4 v2 = has2 ? __ldcs(&s4[i2]) : make_float4(0.f, 0.f, 0.f, 0.f);

    // --- MC keep-count, warp-cooperative (hides under in-flight loads) ---
    float ax, ay;
    ax = p.x - __ldg(&mc[2 * lane + 0]);
    ay = p.y - __ldg(&mc[2 * lane + 1]);
    const bool f0 = (ax * ax + ay * ay) > DROPOUT2;

    ax = p.x - __ldg(&mc[2 * (lane + 32) + 0]);
    ay = p.y - __ldg(&mc[2 * (lane + 32) + 1]);
    const bool f1 = (ax * ax + ay * ay) > DROPOUT2;

    ax = p.x - __ldg(&mc[2 * (lane + 64) + 0]);
    ay = p.y - __ldg(&mc[2 * (lane + 64) + 1]);
    const bool f2 = (ax * ax + ay * ay) > DROPOUT2;

    bool f3 = false;
    if (lane < 4) {
        ax = p.x - __ldg(&mc[2 * (lane + 96) + 0]);
        ay = p.y - __ldg(&mc[2 * (lane + 96) + 1]);
        f3 = (ax * ax + ay * ay) > DROPOUT2;
    }

    const unsigned b0 = __ballot_sync(0xFFFFFFFFu, f0);
    const unsigned b1 = __ballot_sync(0xFFFFFFFFu, f1);
    const unsigned b2 = __ballot_sync(0xFFFFFFFFu, f2);
    const unsigned b3 = __ballot_sync(0xFFFFFFFFu, f3);

    const int cnt = __popc(b0) + __popc(b1) + __popc(b2) + __popc(b3 & 0xFu);

    const float proba = __int2float_rn(cnt) * 0.01f;
    const float scale = 1.0f / (EPSILON + proba);

    // --- scale + streaming stores ---
    v0.x *= scale; v0.y *= scale; v0.z *= scale; v0.w *= scale;
    v1.x *= scale; v1.y *= scale; v1.z *= scale; v1.w *= scale;
    __stcs(&o4[i0], v0);
    __stcs(&o4[i1], v1);
    if (has2) {
        v2.x *= scale; v2.y *= scale; v2.z *= scale; v2.w *= scale;
        __stcs(&o4[i2], v2);
    }
}

extern "C" void kernel_launch(void* const* d_in, const int* in_sizes, int n_in,
                              void* d_out, int out_size)
{
    const float* sig    = (const float*)d_in[0];   // (64, 273, 3000) f32
    const float2* pos2  = (const float2*)d_in[1];  // (64, 273, 2)    f32
    const float* center = (const float*)d_in[2];   // (2,)            f32
    const float* mc     = (const float*)d_in[3];   // (100, 2)        f32
    float* out          = (float*)d_out;

    fused_kernel<<<ROWS * 2, 128>>>(sig, pos2, center, mc, out);
}